// round 17
// baseline (speedup 1.0000x reference)
#include <cuda_runtime.h>
#include <cuda_fp16.h>
#include <math.h>
#include <stdint.h>

#define Bb 8
#define Nn 2048
#define Ff 64
#define MTILE 64
#define JT 64
#define NSTEPS (Nn / JT)        // 32

#define PREP_CTAS 256           // 64 rows each
#define PACK_CTAS 256           // 8 adj rows each

typedef unsigned long long ull;

// Scratch (device globals)
__device__ __half g_WhT[Bb * Ff * Nn];    // 2 MB f16  [b][f][j]
__device__ float4 g_e1pack[Bb * Nn];      // (e1, exp(e1), exp(0.2 e1), 0)
__device__ float4 g_e2pack[Bb * Nn];
__device__ ull    g_adjmask[Nn * (Nn / 64)];   // [i][32 step-words]

// ------------------------- helpers ----------------------------
__device__ __forceinline__ uint32_t smem_u32(const void* p) {
    uint32_t a;
    asm("{ .reg .u64 t; cvta.to.shared.u64 t, %1; cvt.u32.u64 %0, t; }" : "=r"(a) : "l"(p));
    return a;
}
__device__ __forceinline__ uint32_t swz128(uint32_t off) {
    return off ^ ((off >> 3) & 0x70);
}
__device__ __forceinline__ void cp16(uint32_t dst, const void* src) {
    asm volatile("cp.async.cg.shared.global [%0], [%1], 16;" :: "r"(dst), "l"(src));
}
__device__ __forceinline__ void cp8(uint32_t dst, const void* src) {
    asm volatile("cp.async.ca.shared.global [%0], [%1], 8;" :: "r"(dst), "l"(src));
}
#define CP_COMMIT() asm volatile("cp.async.commit_group;" ::: "memory")
#define CP_WAIT0()  asm volatile("cp.async.wait_group 0;" ::: "memory")
__device__ __forceinline__ void ldsm_x4(uint32_t& r0, uint32_t& r1, uint32_t& r2, uint32_t& r3,
                                        uint32_t addr) {
    asm volatile("ldmatrix.sync.aligned.m8n8.x4.shared.b16 {%0,%1,%2,%3}, [%4];"
                 : "=r"(r0), "=r"(r1), "=r"(r2), "=r"(r3) : "r"(addr));
}
__device__ __forceinline__ void mma16816(float* c, const uint32_t* a, const uint32_t* bf) {
    asm volatile(
        "mma.sync.aligned.m16n8k16.row.col.f32.f16.f16.f32 "
        "{%0,%1,%2,%3}, {%4,%5,%6,%7}, {%8,%9}, {%0,%1,%2,%3};"
        : "+f"(c[0]), "+f"(c[1]), "+f"(c[2]), "+f"(c[3])
        : "r"(a[0]), "r"(a[1]), "r"(a[2]), "r"(a[3]), "r"(bf[0]), "r"(bf[1]));
}

// ---------------------------------------------------------------------------
// Kernel 1 (merged prep + bitpack) — unchanged from R16.
// ---------------------------------------------------------------------------
__global__ __launch_bounds__(256) void prep_pack_kernel(const float* __restrict__ h,
                                                        const float* __restrict__ W,
                                                        const float* __restrict__ a,
                                                        const float* __restrict__ adj)
{
    const int t    = threadIdx.x;
    const int lane = t & 31;
    const int w    = t >> 5;      // 0..7

    if (blockIdx.x >= PREP_CTAS) {
        const int row = (blockIdx.x - PREP_CTAS) * 8 + w;
        uint32_t* mw = (uint32_t*)g_adjmask;
        const float* arow = adj + (size_t)row * Nn;
#pragma unroll 4
        for (int c = 0; c < 64; c++) {
            float av = __ldg(&arow[c * 32 + lane]);
            uint32_t m = __ballot_sync(0xffffffffu, av > 0.f);
            if (lane == 0) mw[row * 64 + c] = m;
        }
        return;
    }

    __shared__ __align__(128) char reg1[16384];
    __shared__ __align__(128) char reg2[16384];
    __shared__ __align__(128) __half B_s[64 * 64];
    __shared__ float u1_s[64], u2_s[64];

    float* W32 = (float*)reg1;
    float* h32 = (float*)reg2;
    __half* tT = (__half*)reg2;

    const int row0 = blockIdx.x * 64;

    const uint32_t r1b = smem_u32(reg1);
    const uint32_t r2b = smem_u32(reg2);
    const uint32_t Bsb = smem_u32(B_s);

    {
        const char* Wsrc = (const char*)W;
        const char* hsrc = (const char*)(h + (size_t)row0 * 64);
#pragma unroll
        for (int q = 0; q < 4; q++) {
            cp16(r1b + (t + q * 256) * 16, Wsrc + (t + q * 256) * 16);
            cp16(r2b + (t + q * 256) * 16, hsrc + (t + q * 256) * 16);
        }
        CP_COMMIT();
        CP_WAIT0();
    }
    __syncthreads();

    {
        const int o = t >> 2, fh = (t & 3) * 16;
        const float* src = W32 + o * 64 + fh;
#pragma unroll
        for (int fo = 0; fo < 8; fo++) {
            float2 v = *(const float2*)(src + 2 * fo);
            *(__half2*)((char*)B_s + swz128((uint32_t)(o * 128 + fh * 2 + fo * 4))) =
                __floats2half2_rn(v.x, v.y);
        }
        if (t < 128) {
            const int half = t >> 6, f = t & 63;
            const float* ap = a + half * 64;
            float acc = 0.f;
#pragma unroll 8
            for (int o2 = 0; o2 < 64; o2++)
                acc += W32[o2 * 64 + f] * __ldg(&ap[o2]);
            if (half == 0) u1_s[f] = acc; else u2_s[f] = acc;
        }
    }
    __syncthreads();

    {
        const int r = t >> 2, fh = (t & 3) * 16;
        const float* src = h32 + r * 64 + fh;
        float acc1 = 0.f, acc2 = 0.f;
#pragma unroll
        for (int fo = 0; fo < 8; fo++) {
            float2 v = *(const float2*)(src + 2 * fo);
            int f = fh + 2 * fo;
            acc1 += v.x * u1_s[f] + v.y * u1_s[f + 1];
            acc2 += v.x * u2_s[f] + v.y * u2_s[f + 1];
            *(__half2*)((char*)reg1 + swz128((uint32_t)(r * 128 + fh * 2 + fo * 4))) =
                __floats2half2_rn(v.x, v.y);
        }
        acc1 += __shfl_xor_sync(0xffffffffu, acc1, 1);
        acc1 += __shfl_xor_sync(0xffffffffu, acc1, 2);
        acc2 += __shfl_xor_sync(0xffffffffu, acc2, 1);
        acc2 += __shfl_xor_sync(0xffffffffu, acc2, 2);
        if ((t & 3) == 0) {
            g_e1pack[row0 + r] = make_float4(acc1, __expf(acc1), __expf(0.2f * acc1), 0.f);
            g_e2pack[row0 + r] = make_float4(acc2, __expf(acc2), __expf(0.2f * acc2), 0.f);
        }
    }
    __syncthreads();

    float acc[4][4];
#pragma unroll
    for (int nf = 0; nf < 4; nf++)
#pragma unroll
        for (int c = 0; c < 4; c++) acc[nf][c] = 0.f;

    const int wm = w & 3, wn = w >> 2;
    {
        const uint32_t xv = (lane & 7) << 4;
        const uint32_t aRowOff = (uint32_t)(wm * 16 + (lane & 7) + ((lane >> 3) & 1) * 8) * 128;
        const uint32_t akbo    = ((lane >> 4) & 1) * 16;
        const uint32_t bRow4   = (uint32_t)(wn * 32 + ((lane >> 4) & 1) * 8 + (lane & 7)) * 128;
        const uint32_t bkb4    = ((lane >> 3) & 1) * 16;
#pragma unroll
        for (int kf = 0; kf < 4; kf++) {
            const uint32_t kb = kf * 32;
            uint32_t a4[4];
            ldsm_x4(a4[0], a4[1], a4[2], a4[3], r1b + aRowOff + ((kb + akbo) ^ xv));
#pragma unroll
            for (int p = 0; p < 2; p++) {
                uint32_t bfr[4];
                ldsm_x4(bfr[0], bfr[1], bfr[2], bfr[3],
                        Bsb + bRow4 + p * 2048 + ((kb + bkb4) ^ xv));
                mma16816(acc[2 * p],     a4, bfr);
                mma16816(acc[2 * p + 1], a4, bfr + 2);
            }
        }
    }
    __syncthreads();

    {
        const int r_lo = wm * 16 + (lane >> 2);
        const int r_hi = r_lo + 8;
#pragma unroll
        for (int nf = 0; nf < 4; nf++) {
            const int c0 = wn * 32 + nf * 8 + 2 * (lane & 3);
            tT[(c0 + 0) * 72 + r_lo] = __float2half_rn(acc[nf][0]);
            tT[(c0 + 1) * 72 + r_lo] = __float2half_rn(acc[nf][1]);
            tT[(c0 + 0) * 72 + r_hi] = __float2half_rn(acc[nf][2]);
            tT[(c0 + 1) * 72 + r_hi] = __float2half_rn(acc[nf][3]);
        }
    }
    __syncthreads();

    {
        const int b  = row0 / Nn;
        const int i0 = row0 % Nn;
        const int o  = t >> 2;
        const int rp = (t & 3) * 16;
        __half* dst = g_WhT + ((size_t)b * Ff + o) * Nn + i0 + rp;
        *(uint4*)(dst)     = *(const uint4*)&tT[o * 72 + rp];
        *(uint4*)(dst + 8) = *(const uint4*)&tT[o * 72 + rp + 8];
    }
}

// ---------------------------------------------------------------------------
// Kernel 2: GAT via HMMA — 128 thr / 4 warps, warp tile 32i x 32f.
// Fragment traffic per step: 32 KB (vs 48 KB with 8 warps at 16x32).
// All loop inputs (B tile, e2 slice, mask words) cp.async-staged, triple-
// buffered; A double-buffered; 1 syncthreads per step, PGEN one step ahead.
// ---------------------------------------------------------------------------
__global__ __launch_bounds__(128, 4) void gat_hmma(float* __restrict__ out)
{
    __shared__ __align__(128) __half B_st[3][64 * 64];   // 24 KB staged B
    __shared__ __align__(128) __half A_s[2][MTILE * 64]; // 16 KB
    __shared__ __align__(16)  float4 e2_st[3][64];       // 3 KB staged e2 packs
    __shared__ __align__(16)  ull    mk_st[3][64];       // 1.5 KB staged masks
    __shared__ __align__(16)  float4 e1q_s[MTILE];       // 1 KB
    __shared__ float Z_s[MTILE];

    const int t    = threadIdx.x;
    const int lane = t & 31;
    const int w    = t >> 5;      // 0..3
    const int wm   = w & 1;       // rows wm*32 .. +31
    const int wn   = w >> 1;      // cols wn*32 .. +31
    const int i0   = blockIdx.x * MTILE;
    const int b    = blockIdx.y;

    if (t < MTILE) e1q_s[t] = g_e1pack[(size_t)b * Nn + i0 + t];

    const uint32_t Bstb = smem_u32(B_st);
    const uint32_t Abase = smem_u32(A_s);
    const uint32_t e2b  = smem_u32(e2_st);
    const uint32_t mkb  = smem_u32(mk_st);

    const uint32_t xv = (lane & 7) << 4;
    const uint32_t aRowOff = (uint32_t)(wm * 32 + (lane & 7) + ((lane >> 3) & 1) * 8) * 128;
    const uint32_t akbo    = ((lane >> 4) & 1) * 16;
    const uint32_t bRow4   = (uint32_t)(wn * 32 + ((lane >> 4) & 1) * 8 + (lane & 7)) * 128;
    const uint32_t bkb4    = ((lane >> 3) & 1) * 16;

    const __half* whtB = g_WhT + (size_t)b * Ff * Nn;
    const float4* e2p  = g_e2pack + (size_t)b * Nn;

    // cp.async B: 512 chunks / 128 thr -> 4 per thread
    const int bc_ = t & 7;

#define CPB(S, SB) do {                                                          \
        _Pragma("unroll")                                                        \
        for (int q = 0; q < 4; q++) {                                            \
            int c = t + q * 128;                                                 \
            int f = c >> 3, ch = c & 7;                                          \
            cp16(Bstb + (SB) * 8192 + swz128((uint32_t)(f * 128 + ch * 16)),     \
                 whtB + (size_t)f * Nn + (S) * JT + ch * 8);                     \
        }                                                                        \
        if (t < 64)                                                              \
            cp16(e2b + (SB) * 1024 + t * 16, e2p + (S) * JT + t);                \
        else                                                                     \
            cp8(mkb + (SB) * 512 + (t - 64) * 8,                                 \
                &g_adjmask[(size_t)(i0 + t - 64) * (Nn / 64) + (S)]);            \
        CP_COMMIT();                                                             \
    } while (0)

    float acc[2][4][4];
#pragma unroll
    for (int m2 = 0; m2 < 2; m2++)
#pragma unroll
        for (int nf = 0; nf < 4; nf++)
#pragma unroll
            for (int c = 0; c < 4; c++) acc[m2][nf][c] = 0.f;

    float zpart[16];
#pragma unroll
    for (int g = 0; g < 16; g++) zpart[g] = 0.f;

    // PGEN: warp w -> rows w*16..+15; lane -> j pair (2*lane, 2*lane+1)
#define PGEN_C(SB, ABUF) do {                                                    \
        float4 jp0 = e2_st[SB][2 * lane];                                        \
        float4 jp1 = e2_st[SB][2 * lane + 1];                                    \
        _Pragma("unroll")                                                        \
        for (int g = 0; g < 16; g++) {                                           \
            int i = w * 16 + g;                                                  \
            ull m = mk_st[SB][i];                                                \
            float4 q = e1q_s[i];                                                 \
            float p0 = (q.x + jp0.x > 0.f) ? q.y * jp0.y : q.z * jp0.z;          \
            float p1 = (q.x + jp1.x > 0.f) ? q.y * jp1.y : q.z * jp1.z;          \
            p0 = ((m >> (2 * lane)) & 1ull)     ? p0 : 0.f;                      \
            p1 = ((m >> (2 * lane + 1)) & 1ull) ? p1 : 0.f;                      \
            __half2 ph = __floats2half2_rn(p0, p1);                              \
            float2 pf = __half22float2(ph);                                      \
            zpart[g] += pf.x + pf.y;                                             \
            *(__half2*)((char*)A_s + (ABUF) * 8192 +                             \
                        swz128((uint32_t)(i * 128 + lane * 4))) = ph;            \
        }                                                                        \
    } while (0)

#define HMMA(ABUF, SB) do {                                                      \
        const uint32_t Ab_ = Abase + (ABUF) * 8192;                              \
        const uint32_t Bb_ = Bstb + (SB) * 8192;                                 \
        _Pragma("unroll")                                                        \
        for (int kf = 0; kf < 4; kf++) {                                         \
            const uint32_t kb = kf * 32;                                         \
            uint32_t a0[4], a1[4], b0[4], b1[4];                                 \
            ldsm_x4(a0[0], a0[1], a0[2], a0[3], Ab_ + aRowOff + ((kb + akbo) ^ xv)); \
            ldsm_x4(a1[0], a1[1], a1[2], a1[3], Ab_ + aRowOff + 2048 + ((kb + akbo) ^ xv)); \
            ldsm_x4(b0[0], b0[1], b0[2], b0[3], Bb_ + bRow4 + ((kb + bkb4) ^ xv)); \
            ldsm_x4(b1[0], b1[1], b1[2], b1[3], Bb_ + bRow4 + 2048 + ((kb + bkb4) ^ xv)); \
            mma16816(acc[0][0], a0, b0); mma16816(acc[0][1], a0, b0 + 2);        \
            mma16816(acc[0][2], a0, b1); mma16816(acc[0][3], a0, b1 + 2);        \
            mma16816(acc[1][0], a1, b0); mma16816(acc[1][1], a1, b0 + 2);        \
            mma16816(acc[1][2], a1, b1); mma16816(acc[1][3], a1, b1 + 2);        \
        }                                                                        \
    } while (0)

    // prologue: stage 0 and 1; PGEN(0)
    CPB(0, 0);
    CPB(1, 1);
    asm volatile("cp.async.wait_group 1;" ::: "memory");   // stage 0 resident
    __syncthreads();
    PGEN_C(0, 0);

    int sb0 = 0, sb1 = 1, sb2 = 2;
#pragma unroll 1
    for (int s = 0; s < NSTEPS; s++) {
        CP_WAIT0();            // stages <= s+1 resident
        __syncthreads();       // staged visible; A[(s+1)&1] free
        if (s + 2 < NSTEPS) CPB(s + 2, sb2);
        if (s + 1 < NSTEPS) PGEN_C(sb1, (s + 1) & 1);
        HMMA(s & 1, sb0);
        int tmp = sb0; sb0 = sb1; sb1 = sb2; sb2 = tmp;
    }
#undef CPB
#undef PGEN_C
#undef HMMA

    // Z reduce (PGEN warp w owns rows w*16..+15)
#pragma unroll
    for (int g = 0; g < 16; g++) {
        float z = zpart[g];
#pragma unroll
        for (int off = 16; off; off >>= 1)
            z += __shfl_xor_sync(0xffffffffu, z, off);
        if (lane == 0) Z_s[w * 16 + g] = z;
    }
    __syncthreads();

    // epilogue: warp covers rows wm*32..+31, cols wn*32..+31
#pragma unroll
    for (int m2 = 0; m2 < 2; m2++) {
        const int r_lo = wm * 32 + m2 * 16 + (lane >> 2);
        const int r_hi = r_lo + 8;
        const float zlo = 1.0f / Z_s[r_lo];
        const float zhi = 1.0f / Z_s[r_hi];
        float* olo = out + ((size_t)b * Nn + i0 + r_lo) * 64;
        float* ohi = out + ((size_t)b * Nn + i0 + r_hi) * 64;
#pragma unroll
        for (int nf = 0; nf < 4; nf++) {
            const int col = wn * 32 + nf * 8 + 2 * (lane & 3);
            float2 v;
            v.x = acc[m2][nf][0] * zlo; v.y = acc[m2][nf][1] * zlo;
            v.x = v.x > 0.f ? v.x : expm1f(v.x);
            v.y = v.y > 0.f ? v.y : expm1f(v.y);
            *(float2*)(olo + col) = v;
            v.x = acc[m2][nf][2] * zhi; v.y = acc[m2][nf][3] * zhi;
            v.x = v.x > 0.f ? v.x : expm1f(v.x);
            v.y = v.y > 0.f ? v.y : expm1f(v.y);
            *(float2*)(ohi + col) = v;
        }
    }
}

// ---------------------------------------------------------------------------
extern "C" void kernel_launch(void* const* d_in, const int* in_sizes, int n_in,
                              void* d_out, int out_size)
{
    const float* h = nullptr; const float* adj = nullptr;
    const float* W = nullptr; const float* a = nullptr;
    for (int i = 0; i < n_in; i++) {
        switch (in_sizes[i]) {
            case Bb * Nn * Ff: h   = (const float*)d_in[i]; break;
            case Nn * Nn:      adj = (const float*)d_in[i]; break;
            case Ff * Ff:      W   = (const float*)d_in[i]; break;
            case 2 * Ff:       a   = (const float*)d_in[i]; break;
            default: break;
        }
    }
    (void)out_size;

    prep_pack_kernel<<<PREP_CTAS + PACK_CTAS, 256>>>(h, W, a, adj);
    gat_hmma<<<dim3(Nn / MTILE, Bb), 128>>>((float*)d_out);
}